// round 3
// baseline (speedup 1.0000x reference)
#include <cuda_runtime.h>
#include <cuda_bf16.h>
#include <math.h>
#include <stdint.h>

// x: (16, 256, 64, 64, 4) f32. Per (b,c) channel slab = 4096 float4 = 64 KB.
// 1024 persistent light blocks in 4 independent pipeline groups of 256.
// Group g handles batches {g, g+4, g+8, g+12}. Pool read fills L2; scale pass
// re-reads from L2 (ldcs) and streams the output (stcs). DRAM: 256MB+256MB.

#define NB 16
#define NC 256
#define SP 4096                 // float4 per (b,c)
#define NGROUPS 4
#define TPB 128
#define V_PER_T (SP / TPB)      // 32 float4 per thread

__device__ float4 g_pooled[NB * NC];
__device__ int    g_cnt[NB];

__device__ __forceinline__ int ld_acquire_gpu(const int* p) {
    int v;
    asm volatile("ld.acquire.gpu.global.s32 %0, [%1];" : "=r"(v) : "l"(p) : "memory");
    return v;
}

__global__ void reset_kernel() {
    if (threadIdx.x < NB) g_cnt[threadIdx.x] = 0;
}

__global__ void __launch_bounds__(TPB, 8)
fused_kernel(const float* __restrict__ x,
             const float* __restrict__ comp_w,
             const float* __restrict__ comp_b,
             const float* __restrict__ exc_w,
             const float* __restrict__ exc_b,
             float* __restrict__ out) {
    __shared__ float4 red[TPB / 32];
    __shared__ float4 u_bcast;

    const int gid  = blockIdx.x >> 8;      // pipeline group 0..3
    const int c    = blockIdx.x & 255;     // channel
    const int t    = threadIdx.x;
    const int lane = t & 31;
    const int warp = t >> 5;

    for (int b = gid; b < NB; b += NGROUPS) {
        const size_t base = (size_t)(b * NC + c) * SP;
        const float4* xp = reinterpret_cast<const float4*>(x) + base;
        float4* op = reinterpret_cast<float4*>(out) + base;

        // ---- Pool: read channel slab (fills L2), per-component max ----
        float4 m = make_float4(-INFINITY, -INFINITY, -INFINITY, -INFINITY);
        #pragma unroll 8
        for (int j = 0; j < V_PER_T; j++) {
            float4 v = xp[t + j * TPB];
            m.x = fmaxf(m.x, v.x);
            m.y = fmaxf(m.y, v.y);
            m.z = fmaxf(m.z, v.z);
            m.w = fmaxf(m.w, v.w);
        }
        #pragma unroll
        for (int o = 16; o > 0; o >>= 1) {
            m.x = fmaxf(m.x, __shfl_xor_sync(0xffffffffu, m.x, o));
            m.y = fmaxf(m.y, __shfl_xor_sync(0xffffffffu, m.y, o));
            m.z = fmaxf(m.z, __shfl_xor_sync(0xffffffffu, m.z, o));
            m.w = fmaxf(m.w, __shfl_xor_sync(0xffffffffu, m.w, o));
        }
        if (lane == 0) red[warp] = m;
        __syncthreads();                                        // S1

        // ---- Publish + per-batch barrier (this group's 256 blocks) ----
        if (t == 0) {
            float4 r = red[0];
            #pragma unroll
            for (int w = 1; w < TPB / 32; w++) {
                r.x = fmaxf(r.x, red[w].x);
                r.y = fmaxf(r.y, red[w].y);
                r.z = fmaxf(r.z, red[w].z);
                r.w = fmaxf(r.w, red[w].w);
            }
            g_pooled[b * NC + c] = r;
            __threadfence();
            atomicAdd(&g_cnt[b], 1);
            while (ld_acquire_gpu(&g_cnt[b]) < NC) __nanosleep(64);
        }
        __syncthreads();                                        // S2

        // ---- Squeeze: dot over 256 channels (2 per thread) ----
        float s0 = 0.f, s1 = 0.f, s2 = 0.f, s3 = 0.f;
        #pragma unroll
        for (int k = 0; k < NC / TPB; k++) {
            int ch = t + k * TPB;
            float4 p = __ldcg(&g_pooled[b * NC + ch]);
            s0 += p.x * comp_w[0 * NC + ch];
            s1 += p.y * comp_w[1 * NC + ch];
            s2 += p.z * comp_w[2 * NC + ch];
            s3 += p.w * comp_w[3 * NC + ch];
        }
        #pragma unroll
        for (int o = 16; o > 0; o >>= 1) {
            s0 += __shfl_xor_sync(0xffffffffu, s0, o);
            s1 += __shfl_xor_sync(0xffffffffu, s1, o);
            s2 += __shfl_xor_sync(0xffffffffu, s2, o);
            s3 += __shfl_xor_sync(0xffffffffu, s3, o);
        }
        if (lane == 0) red[warp] = make_float4(s0, s1, s2, s3);
        __syncthreads();                                        // S3

        if (t == 0) {
            float r  = comp_b[0];
            float xc = comp_b[1];
            float yc = comp_b[2];
            float zc = comp_b[3];
            #pragma unroll
            for (int w = 0; w < TPB / 32; w++) {
                r  += red[w].x;
                xc += red[w].y;
                yc += red[w].z;
                zc += red[w].w;
            }
            float u1r = r + xc + yc + zc;
            float u1x = xc - r - zc + yc;
            float u1y = yc + zc - r - xc;
            float u1z = zc - yc + xc - r;
            float r2 = u1r * exc_w[0 * NC + c] + exc_b[0 * NC + c];
            float x2 = u1x * exc_w[1 * NC + c] + exc_b[1 * NC + c];
            float y2 = u1y * exc_w[2 * NC + c] + exc_b[2 * NC + c];
            float z2 = u1z * exc_w[3 * NC + c] + exc_b[3 * NC + c];
            u_bcast = make_float4(r2 + x2 + y2 + z2,
                                  x2 - r2 - z2 + y2,
                                  y2 + z2 - r2 - x2,
                                  z2 - y2 + x2 - r2);
        }
        __syncthreads();                                        // S4
        float4 u = u_bcast;

        // ---- Scale: re-read slab (L2 hit, evict-first), stream out ----
        #pragma unroll 8
        for (int j = 0; j < V_PER_T; j++) {
            int idx = t + j * TPB;
            float4 s = __ldcs(&xp[idx]);
            __stcs(&op[idx], make_float4(s.x * u.x, s.y * u.y,
                                         s.z * u.z, s.w * u.w));
        }
    }
}

extern "C" void kernel_launch(void* const* d_in, const int* in_sizes, int n_in,
                              void* d_out, int out_size) {
    const float* x      = (const float*)d_in[0];
    const float* comp_w = (const float*)d_in[1];
    const float* comp_b = (const float*)d_in[2];
    const float* exc_w  = (const float*)d_in[3];
    const float* exc_b  = (const float*)d_in[4];
    float* out = (float*)d_out;

    reset_kernel<<<1, 32>>>();
    fused_kernel<<<NGROUPS * NC, TPB>>>(x, comp_w, comp_b, exc_w, exc_b, out);
}

// round 4
// speedup vs baseline: 1.1023x; 1.1023x over previous
#include <cuda_runtime.h>
#include <cuda_bf16.h>
#include <math.h>
#include <stdint.h>

// x: (16, 256, 64, 64, 4) f32. Per (b,c) slab = 4096 float4 = 1 MB... no: 64 KB.
// Strategy: process in 2 halves of 8 batches (128 MB each ~ L2 capacity).
//   pool(half):  read half from DRAM (fills L2), write per-(b,c) max.
//   scale(half): traverse in REVERSE block order so x reads hit L2;
//                excite computed redundantly per block; writes streamed (stcs).
// DRAM traffic ~ 256 read + 256 write + L2 spill, vs 768 MB unfused.

#define NB 16
#define NC 256
#define SP 4096              // float4 per (b,c)
#define HALF_B 8
#define HALF_BLOCKS (HALF_B * NC)   // 2048
#define TPB 256
#define V_PER_T (SP / TPB)   // 16 float4 per thread

__device__ float4 g_pooled[NB * NC];

// ---------------------------------------------------------------------------
// Pool: one block per (b,c) within the half. Ascending block order.
// ---------------------------------------------------------------------------
__global__ void __launch_bounds__(TPB) pool_kernel(const float* __restrict__ x,
                                                   int b0) {
    const int bc = b0 * NC + blockIdx.x;
    const float4* xp = reinterpret_cast<const float4*>(x) + (size_t)bc * SP;

    float4 m = make_float4(-INFINITY, -INFINITY, -INFINITY, -INFINITY);
    #pragma unroll
    for (int j = 0; j < V_PER_T; j++) {
        float4 v = xp[threadIdx.x + j * TPB];
        m.x = fmaxf(m.x, v.x);
        m.y = fmaxf(m.y, v.y);
        m.z = fmaxf(m.z, v.z);
        m.w = fmaxf(m.w, v.w);
    }
    #pragma unroll
    for (int o = 16; o > 0; o >>= 1) {
        m.x = fmaxf(m.x, __shfl_xor_sync(0xffffffffu, m.x, o));
        m.y = fmaxf(m.y, __shfl_xor_sync(0xffffffffu, m.y, o));
        m.z = fmaxf(m.z, __shfl_xor_sync(0xffffffffu, m.z, o));
        m.w = fmaxf(m.w, __shfl_xor_sync(0xffffffffu, m.w, o));
    }
    __shared__ float4 red[TPB / 32];
    const int lane = threadIdx.x & 31;
    const int warp = threadIdx.x >> 5;
    if (lane == 0) red[warp] = m;
    __syncthreads();
    if (threadIdx.x == 0) {
        float4 r = red[0];
        #pragma unroll
        for (int w = 1; w < TPB / 32; w++) {
            r.x = fmaxf(r.x, red[w].x);
            r.y = fmaxf(r.y, red[w].y);
            r.z = fmaxf(r.z, red[w].z);
            r.w = fmaxf(r.w, red[w].w);
        }
        g_pooled[bc] = r;
    }
}

// ---------------------------------------------------------------------------
// Scale: one block per (b,c) within the half, REVERSE order vs pool.
// Squeeze+excite computed redundantly per block (reads 4 KB of g_pooled
// from L2). Then out = x * u, x read from L2, out streamed.
// ---------------------------------------------------------------------------
__global__ void __launch_bounds__(TPB) scale_kernel(const float* __restrict__ x,
                                                    const float* __restrict__ comp_w,
                                                    const float* __restrict__ comp_b,
                                                    const float* __restrict__ exc_w,
                                                    const float* __restrict__ exc_b,
                                                    float* __restrict__ out,
                                                    int b0) {
    const int ridx = HALF_BLOCKS - 1 - blockIdx.x;   // reverse traversal
    const int b = b0 + (ridx >> 8);
    const int c = ridx & 255;
    const int t = threadIdx.x;
    const int lane = t & 31;
    const int warp = t >> 5;

    __shared__ float4 red[TPB / 32];
    __shared__ float4 u_sh;

    // ---- Squeeze: dot(pooled[b,:], comp_w), thread t = channel t ----
    float4 p = g_pooled[b * NC + t];
    float s0 = p.x * comp_w[0 * NC + t];
    float s1 = p.y * comp_w[1 * NC + t];
    float s2 = p.z * comp_w[2 * NC + t];
    float s3 = p.w * comp_w[3 * NC + t];
    #pragma unroll
    for (int o = 16; o > 0; o >>= 1) {
        s0 += __shfl_xor_sync(0xffffffffu, s0, o);
        s1 += __shfl_xor_sync(0xffffffffu, s1, o);
        s2 += __shfl_xor_sync(0xffffffffu, s2, o);
        s3 += __shfl_xor_sync(0xffffffffu, s3, o);
    }
    if (lane == 0) red[warp] = make_float4(s0, s1, s2, s3);
    __syncthreads();
    if (t == 0) {
        float r  = comp_b[0];
        float xc = comp_b[1];
        float yc = comp_b[2];
        float zc = comp_b[3];
        #pragma unroll
        for (int w = 0; w < TPB / 32; w++) {
            r  += red[w].x;
            xc += red[w].y;
            yc += red[w].z;
            zc += red[w].w;
        }
        float u1r = r + xc + yc + zc;
        float u1x = xc - r - zc + yc;
        float u1y = yc + zc - r - xc;
        float u1z = zc - yc + xc - r;
        float r2 = u1r * exc_w[0 * NC + c] + exc_b[0 * NC + c];
        float x2 = u1x * exc_w[1 * NC + c] + exc_b[1 * NC + c];
        float y2 = u1y * exc_w[2 * NC + c] + exc_b[2 * NC + c];
        float z2 = u1z * exc_w[3 * NC + c] + exc_b[3 * NC + c];
        u_sh = make_float4(r2 + x2 + y2 + z2,
                           x2 - r2 - z2 + y2,
                           y2 + z2 - r2 - x2,
                           z2 - y2 + x2 - r2);
    }
    __syncthreads();
    const float4 u = u_sh;

    // ---- Scale slab: read (L2 hit expected), write streamed ----
    const size_t base = (size_t)(b * NC + c) * SP;
    const float4* xp = reinterpret_cast<const float4*>(x) + base;
    float4* op = reinterpret_cast<float4*>(out) + base;
    #pragma unroll
    for (int j = 0; j < V_PER_T; j++) {
        int idx = t + j * TPB;
        float4 s = __ldcs(&xp[idx]);
        __stcs(&op[idx], make_float4(s.x * u.x, s.y * u.y,
                                     s.z * u.z, s.w * u.w));
    }
}

extern "C" void kernel_launch(void* const* d_in, const int* in_sizes, int n_in,
                              void* d_out, int out_size) {
    const float* x      = (const float*)d_in[0];
    const float* comp_w = (const float*)d_in[1];
    const float* comp_b = (const float*)d_in[2];
    const float* exc_w  = (const float*)d_in[3];
    const float* exc_b  = (const float*)d_in[4];
    float* out = (float*)d_out;

    pool_kernel <<<HALF_BLOCKS, TPB>>>(x, 0);
    scale_kernel<<<HALF_BLOCKS, TPB>>>(x, comp_w, comp_b, exc_w, exc_b, out, 0);
    pool_kernel <<<HALF_BLOCKS, TPB>>>(x, HALF_B);
    scale_kernel<<<HALF_BLOCKS, TPB>>>(x, comp_w, comp_b, exc_w, exc_b, out, HALF_B);
}